// round 14
// baseline (speedup 1.0000x reference)
#include <cuda_runtime.h>
#include <cuda_bf16.h>
#include <math.h>

#define S_LEN 120
#define T_LEN 10
#define B_SZ  128
#define E_DIM 80
#define HW    75
#define HWP   76
#define HS    700
#define NW    (S_LEN * B_SZ)   /* 15360 word-level batch */

typedef __nv_bfloat16 bf;

#define XE_N    (T_LEN * NW * E_DIM)
#define XW_N    (2L * T_LEN * NW * (3 * HW))
#define Y0W_N   (T_LEN * NW * 2 * HW)
#define WORDS_N (NW * 4 * HW)
#define Y0S_N   ((long)S_LEN * B_SZ * 2 * HS)
#define HWBUF_N (2 * NW * HWP)
#define HSBUF_N (2 * B_SZ * HS)

#define NBLK_S  88            /* sentence persistent: 2 dirs x 44 hc tiles of 16 */
#define DIRB_S  44
#define WSTRW   356           /* u32 stride of sentence W smem row */
#define SMEM_PERS (2 * 48 * WSTRW * 4)       /* 136704 B */

#define WQ      41            /* u32 stride of word W smem row */
#define WORD_SMEM (2 * 240 * WQ * 4)         /* 78720 B */

#define GSTR    40            /* bf stride of GEMM smem row */
#define GEMM_SMEM (2 * 4 * 128 * GSTR * 2)   /* 81920 B */

/* ---------------- persistent scratch (device globals; no allocs) ------------- */
__device__ bf    g_xe_b[XE_N],    g_xe_s[XE_N];
__device__ float g_xw[XW_N];
__device__ bf    g_y0w_b[Y0W_N],  g_y0w_s[Y0W_N];
__device__ bf    g_words_b[WORDS_N], g_words_s[WORDS_N];
__device__ bf    g_y0s_b[Y0S_N],  g_y0s_s[Y0S_N];
__device__ float g_hwf[2][HWBUF_N];
__device__ float g_hsf[4][HSBUF_N];
__device__ bf    g_hsb[4][HSBUF_N], g_hss[4][HSBUF_N];
__device__ unsigned g_bar[2];
/* weight splits */
__device__ bf g_weWih0_b[2*3*HW*E_DIM],  g_weWih0_s[2*3*HW*E_DIM];
__device__ bf g_weWih1_b[2*3*HW*2*HW],   g_weWih1_s[2*3*HW*2*HW];
__device__ bf g_weWhh0_b[2*3*HW*HWP],    g_weWhh0_s[2*3*HW*HWP];
__device__ bf g_weWhh1_b[2*3*HW*HWP],    g_weWhh1_s[2*3*HW*HWP];
__device__ bf g_seWih0_b[2*3*HS*4*HW],   g_seWih0_s[2*3*HS*4*HW];
__device__ bf g_seWih1_b[2*3*HS*2*HS],   g_seWih1_s[2*3*HS*2*HS];
__device__ bf g_seWhh0_b[2*3*HS*HS],     g_seWhh0_s[2*3*HS*HS];
__device__ bf g_seWhh1_b[2*3*HS*HS],     g_seWhh1_s[2*3*HS*HS];

/* ---------------- helpers ---------------------------------------------------- */
__device__ __forceinline__ void bsplit(float v, bf &b, bf &s) {
    b = __float2bfloat16_rn(v);
    s = __float2bfloat16_rn(v - __bfloat162float(b));
}
__device__ __forceinline__ void mma16(float d[4], const unsigned a[4],
                                      unsigned b0, unsigned b1) {
    asm volatile(
        "mma.sync.aligned.m16n8k16.row.col.f32.bf16.bf16.f32 "
        "{%0,%1,%2,%3},{%4,%5,%6,%7},{%8,%9},{%0,%1,%2,%3};"
        : "+f"(d[0]), "+f"(d[1]), "+f"(d[2]), "+f"(d[3])
        : "r"(a[0]), "r"(a[1]), "r"(a[2]), "r"(a[3]), "r"(b0), "r"(b1));
}
__device__ __forceinline__ void ldsm4(unsigned (&r)[4], unsigned addr) {
    asm volatile("ldmatrix.sync.aligned.m8n8.x4.shared.b16 {%0,%1,%2,%3}, [%4];"
        : "=r"(r[0]), "=r"(r[1]), "=r"(r[2]), "=r"(r[3]) : "r"(addr));
}
__device__ __forceinline__ void cpasync4(unsigned saddr, const void* g, bool p) {
    asm volatile("cp.async.ca.shared.global [%0], [%1], 4, %2;"
                 :: "r"(saddr), "l"(g), "r"(p ? 4u : 0u));
}
__device__ __forceinline__ void cp_commit() { asm volatile("cp.async.commit_group;"); }
__device__ __forceinline__ void cp_wait1()  { asm volatile("cp.async.wait_group 1;"); }
__device__ __forceinline__ void cp_wait0()  { asm volatile("cp.async.wait_group 0;"); }

/* ---------------- merged weight split (all 8 tensors, one launch) ------------- */
__device__ __forceinline__ void do_split(const float* W, bf* b, bf* s,
                                         long rel, int K, int KP) {
    int k = (int)(rel % KP);
    long r = rel / KP;
    float v = (k < K) ? W[r * K + k] : 0.f;
    bf vb, vs; bsplit(v, vb, vs);
    b[rel] = vb; s[rel] = vs;
}
__global__ void split_all(
    const float* W0, bf* b0, bf* s0, const float* W1, bf* b1, bf* s1,
    const float* W2, bf* b2, bf* s2, const float* W3, bf* b3, bf* s3,
    const float* W4, bf* b4, bf* s4, const float* W5, bf* b5, bf* s5,
    const float* W6, bf* b6, bf* s6, const float* W7, bf* b7, bf* s7)
{
    const long N0 = 450L*80,  C0 = N0;
    const long N1 = 450L*150, C1 = C0 + N1;
    const long N2 = 450L*76,  C2 = C1 + N2;
    const long N3 = 450L*76,  C3 = C2 + N3;
    const long N4 = 4200L*300,  C4 = C3 + N4;
    const long N5 = 4200L*1400, C5 = C4 + N5;
    const long N6 = 4200L*700,  C6 = C5 + N6;
    const long N7 = 4200L*700,  C7 = C6 + N7;
    long idx = blockIdx.x * 256L + threadIdx.x;
    if (idx >= C7) return;
    if      (idx < C0) do_split(W0, b0, s0, idx,        80,   80);
    else if (idx < C1) do_split(W1, b1, s1, idx - C0,   150,  150);
    else if (idx < C2) do_split(W2, b2, s2, idx - C1,   75,   76);
    else if (idx < C3) do_split(W3, b3, s3, idx - C2,   75,   76);
    else if (idx < C4) do_split(W4, b4, s4, idx - C3,   300,  300);
    else if (idx < C5) do_split(W5, b5, s5, idx - C4,   1400, 1400);
    else if (idx < C6) do_split(W6, b6, s6, idx - C5,   700,  700);
    else               do_split(W7, b7, s7, idx - C6,   700,  700);
}
#define SPLIT_TOTAL (450L*80 + 450L*150 + 450L*76 + 450L*76 + 4200L*300 + 4200L*1400 + 4200L*700 + 4200L*700)

/* ---------------- embedding gather + split ----------------------------------- */
__global__ void embed_split_k(const int* __restrict__ x, const float* __restrict__ emb,
                              bf* __restrict__ xb, bf* __restrict__ xs) {
    long idx = blockIdx.x * 256L + threadIdx.x;
    if (idx >= XE_N) return;
    int e = (int)(idx % E_DIM);
    int n = (int)((idx / E_DIM) % NW);
    int t = (int)(idx / ((long)E_DIM * NW));
    int s = n >> 7, bb_ = n & 127;
    int tok = x[(s * T_LEN + t) * B_SZ + bb_];
    float v = emb[(long)tok * E_DIM + e];
    bf vb, vs; bsplit(v, vb, vs);
    xb[idx] = vb; xs[idx] = vs;
}

/* -------- C[m][g] = bias[g] + A[m,:]·W[g,:]  (split A & W, 3-mma, LDSM) ------ */
__global__ __launch_bounds__(256) void mma_gemm_bias(
    const bf* __restrict__ Ab_g, const bf* __restrict__ As_g,
    const bf* __restrict__ Wb_g, const bf* __restrict__ Ws_g,
    const float* __restrict__ bias, float* __restrict__ C,
    int M, int G, int K)
{
    extern __shared__ __align__(16) bf gsm[];   /* [2 buf][4 arr][128][GSTR] */
    unsigned sbase = (unsigned)__cvta_generic_to_shared(gsm);
    int tid = threadIdx.x, lane = tid & 31, wid = tid >> 5;
    int gid = lane >> 2, tig = lane & 3;
    int wm = wid & 3, wn = wid >> 2;
    int row0 = blockIdx.y * 128, col0 = blockIdx.x * 128;
    int lrow = lane & 15, lcol8 = (lane >> 4) << 3;

    float acc[2][8][4];
#pragma unroll
    for (int mt = 0; mt < 2; mt++)
#pragma unroll
        for (int nt = 0; nt < 8; nt++)
#pragma unroll
            for (int i = 0; i < 4; i++) acc[mt][nt][i] = 0.f;

    auto fill = [&](int buf, int k0) {
#pragma unroll
        for (int j = 0; j < 32; j++) {
            int e = j * 256 + tid;
            int arr = e >> 11;
            int rem = e & 2047;
            int row = rem >> 4, kk = rem & 15;
            int gk = k0 + 2 * kk;
            unsigned sa = sbase + (unsigned)((((buf * 4 + arr) * 128 + row) * (GSTR/2) + kk) * 4);
            const bf* gp; bool v;
            if (arr < 2) {
                v = (gk < K) && (row0 + row < M);
                gp = (arr ? As_g : Ab_g) + (v ? ((long)(row0 + row) * K + gk) : 0);
            } else {
                int gc = col0 + row;
                v = (gk < K) && (gc < G);
                gp = (arr == 2 ? Wb_g : Ws_g) + (v ? ((long)gc * K + gk) : 0);
            }
            cpasync4(sa, gp, v);
        }
        cp_commit();
    };

    fill(0, 0);
    int buf = 0;
    for (int k0 = 0; k0 < K; k0 += 32) {
        bool more = (k0 + 32 < K);
        if (more) fill(1 - buf, k0 + 32);
        if (more) cp_wait1(); else cp_wait0();
        __syncthreads();

        unsigned base0 = sbase + (unsigned)(2 * (buf * 4) * 128 * GSTR);
        unsigned arrStride = (unsigned)(2 * 128 * GSTR);
#pragma unroll
        for (int kc = 0; kc < 32; kc += 16) {
            unsigned Ab[2][4], As[2][4];
#pragma unroll
            for (int mt = 0; mt < 2; mt++) {
                int row = wm * 32 + mt * 16 + lrow;
                unsigned off = (unsigned)((row * GSTR + kc + lcol8) * 2);
                ldsm4(Ab[mt], base0 + off);
                ldsm4(As[mt], base0 + arrStride + off);
            }
#pragma unroll
            for (int p = 0; p < 4; p++) {
                int row = wn * 64 + p * 16 + lrow;
                unsigned off = (unsigned)((row * GSTR + kc + lcol8) * 2);
                unsigned Bb[4], Bs[4];
                ldsm4(Bb, base0 + 2 * arrStride + off);
                ldsm4(Bs, base0 + 3 * arrStride + off);
#pragma unroll
                for (int sub = 0; sub < 2; sub++) {
                    int nt = 2 * p + sub;
                    unsigned bb0 = Bb[sub], bb1 = Bb[2 + sub];
                    unsigned bs0 = Bs[sub], bs1 = Bs[2 + sub];
#pragma unroll
                    for (int mt = 0; mt < 2; mt++) {
                        mma16(acc[mt][nt], Ab[mt], bb0, bb1);
                        mma16(acc[mt][nt], Ab[mt], bs0, bs1);
                        mma16(acc[mt][nt], As[mt], bb0, bb1);
                    }
                }
            }
        }
        __syncthreads();
        buf = 1 - buf;
    }
#pragma unroll
    for (int mt = 0; mt < 2; mt++)
#pragma unroll
        for (int nt = 0; nt < 8; nt++)
#pragma unroll
            for (int i = 0; i < 4; i++) {
                int gr = row0 + wm * 32 + mt * 16 + gid + 8 * (i >> 1);
                int gc = col0 + wn * 64 + nt * 8 + tig * 2 + (i & 1);
                if (gr < M && gc < G)
                    C[(long)gr * G + gc] = acc[mt][nt][i] + bias[gc];
            }
}

/* -------- word GRU: register-resident h across ALL 10 timesteps -------------- */
__global__ __launch_bounds__(128) void gru_word_persistent(
    float* __restrict__ hf_out,
    const float* __restrict__ xw,
    const bf* __restrict__ Whh_b, const bf* __restrict__ Whh_s,
    const float* __restrict__ bhh,
    bf* __restrict__ y_b, bf* __restrict__ y_s)
{
    extern __shared__ __align__(16) unsigned Wsm[];   /* [2][240][WQ] */
    int tid = threadIdx.x, lane = tid & 31, wid = tid >> 5;
    int gid = lane >> 2, tig = lane & 3;
    int dir = blockIdx.x / 240;
    int n0 = (blockIdx.x % 240) * 64;
    int mrow = wid * 16;

    for (int e = tid; e < 2 * 240 * WQ; e += 128) {
        int arr = e / (240 * WQ);
        int rem = e % (240 * WQ);
        int r = rem / WQ, w = rem % WQ;
        int gate = r / 80, hcl = r % 80;
        unsigned v = 0;
        if (hcl < 75 && w < 38) {
            const bf* src = (arr ? Whh_s : Whh_b) +
                            ((long)(dir * 3 + gate) * 75 + hcl) * HWP + 2 * w;
            v = *(const unsigned*)src;
        }
        Wsm[(arr * 240 + r) * WQ + w] = v;
    }
    __syncthreads();

    unsigned hbf[5][4], hsf[5][4];
    float hpf[5][4][2];
#pragma unroll
    for (int kt = 0; kt < 5; kt++)
#pragma unroll
        for (int j = 0; j < 4; j++) {
            hbf[kt][j] = 0u; hsf[kt][j] = 0u;
            hpf[kt][j][0] = 0.f; hpf[kt][j][1] = 0.f;
        }

    for (int s = 0; s < T_LEN; s++) {
        int t = dir ? (T_LEN - 1 - s) : s;
        unsigned nhb[5][4], nhs[5][4];
#pragma unroll
        for (int ntg = 0; ntg < 10; ntg++) {
            float ar[4] = {0.f,0.f,0.f,0.f};
            float az[4] = {0.f,0.f,0.f,0.f};
            float an[4] = {0.f,0.f,0.f,0.f};
#pragma unroll
            for (int kt = 0; kt < 5; kt++) {
                int cr = ntg * 8 + gid;
                int ko = kt * 8 + tig;
                unsigned rb0 = Wsm[(0 * 240 + cr) * WQ + ko];
                unsigned rb1 = Wsm[(0 * 240 + cr) * WQ + ko + 4];
                unsigned rs0 = Wsm[(1 * 240 + cr) * WQ + ko];
                unsigned rs1 = Wsm[(1 * 240 + cr) * WQ + ko + 4];
                unsigned zb0 = Wsm[(0 * 240 + 80 + cr) * WQ + ko];
                unsigned zb1 = Wsm[(0 * 240 + 80 + cr) * WQ + ko + 4];
                unsigned zs0 = Wsm[(1 * 240 + 80 + cr) * WQ + ko];
                unsigned zs1 = Wsm[(1 * 240 + 80 + cr) * WQ + ko + 4];
                unsigned nb0 = Wsm[(0 * 240 + 160 + cr) * WQ + ko];
                unsigned nb1 = Wsm[(0 * 240 + 160 + cr) * WQ + ko + 4];
                unsigned ns0 = Wsm[(1 * 240 + 160 + cr) * WQ + ko];
                unsigned ns1 = Wsm[(1 * 240 + 160 + cr) * WQ + ko + 4];
                mma16(ar, hbf[kt], rb0, rb1);
                mma16(ar, hbf[kt], rs0, rs1);
                mma16(ar, hsf[kt], rb0, rb1);
                mma16(az, hbf[kt], zb0, zb1);
                mma16(az, hbf[kt], zs0, zs1);
                mma16(az, hsf[kt], zb0, zb1);
                mma16(an, hbf[kt], nb0, nb1);
                mma16(an, hbf[kt], ns0, ns1);
                mma16(an, hsf[kt], nb0, nb1);
            }
            int kt_e = ntg >> 1, half = ntg & 1;
#pragma unroll
            for (int ii = 0; ii < 2; ii++) {
                int n = n0 + mrow + gid + 8 * ii;
                int j = 2 * half + ii;
                unsigned hb2 = 0u, hs2 = 0u;
#pragma unroll
                for (int par = 0; par < 2; par++) {
                    int hc = ntg * 8 + tig * 2 + par;
                    float hn = 0.f;
                    bf b_ = __float2bfloat16_rn(0.f), s_ = b_;
                    if (hc < 75) {
                        float hp = hpf[kt_e][j][par];
                        long xb = ((long)(dir * T_LEN + t) * NW + n) * 225;
                        float xr = xw[xb + hc];
                        float xz = xw[xb + 75 + hc];
                        float xn = xw[xb + 150 + hc];
                        float gr_ = ar[ii * 2 + par] + bhh[dir * 225 + hc];
                        float gz_ = az[ii * 2 + par] + bhh[dir * 225 + 75 + hc];
                        float gn_ = an[ii * 2 + par] + bhh[dir * 225 + 150 + hc];
                        float rg = 1.f / (1.f + expf(-(xr + gr_)));
                        float zg = 1.f / (1.f + expf(-(xz + gz_)));
                        float ng = tanhf(xn + rg * gn_);
                        hn = (1.f - zg) * ng + zg * hp;
                        bsplit(hn, b_, s_);
                        if (y_b) {
                            long yi = ((long)t * NW + n) * 150 + (long)dir * 75 + hc;
                            y_b[yi] = b_; y_s[yi] = s_;
                        }
                    }
                    hpf[kt_e][j][par] = hn;
                    hb2 |= (unsigned)__bfloat16_as_ushort(b_) << (16 * par);
                    hs2 |= (unsigned)__bfloat16_as_ushort(s_) << (16 * par);
                }
                nhb[kt_e][j] = hb2;
                nhs[kt_e][j] = hs2;
            }
        }
#pragma unroll
        for (int kt = 0; kt < 5; kt++)
#pragma unroll
            for (int j = 0; j < 4; j++) {
                hbf[kt][j] = nhb[kt][j];
                hsf[kt][j] = nhs[kt][j];
            }
    }

#pragma unroll
    for (int kt = 0; kt < 5; kt++)
#pragma unroll
        for (int j = 0; j < 4; j++)
#pragma unroll
            for (int par = 0; par < 2; par++) {
                int n = n0 + mrow + gid + 8 * (j & 1);
                int hc = kt * 16 + (j >> 1) * 8 + tig * 2 + par;
                if (hc < 75)
                    hf_out[((long)dir * NW + n) * HWP + hc] = hpf[kt][j][par];
            }
}

/* -------- persistent sentence GRU: 88 blocks, Whh in SMEM (LDSM), direct
   global h fragments, depth-2 prefetch, hoisted bias/xw, per-dir barriers. --- */
__global__ __launch_bounds__(256) void gru_sent_persistent(
    const bf* __restrict__ Whh_b, const bf* __restrict__ Whh_s,
    const float* __restrict__ bhh, const float* __restrict__ xw,
    float* __restrict__ hfA, bf* __restrict__ hbA, bf* __restrict__ hsA,
    float* __restrict__ hfB, bf* __restrict__ hbB, bf* __restrict__ hsB,
    bf* __restrict__ y_b, bf* __restrict__ y_s, unsigned* __restrict__ bar)
{
    extern __shared__ __align__(16) unsigned smem_u[];
    unsigned* Wu = smem_u;                       /* [2][48][WSTRW] */
    unsigned wu_sb = (unsigned)__cvta_generic_to_shared(smem_u);

    int tid = threadIdx.x, lane = tid & 31, wid = tid >> 5;
    int gid = lane >> 2, tig = lane & 3;
    int dir = blockIdx.x / DIRB_S;
    int h0 = (blockIdx.x % DIRB_S) * 16;
    int mrow = wid * 16;
    int lrow = lane & 15, lcol4 = (lane >> 4) << 2;

    for (int e = tid; e < 2 * 48 * 352; e += 256) {
        int arr = e / (48 * 352);
        int rem = e % (48 * 352);
        int r = rem / 352, w = rem % 352;
        int gate = r >> 4, hc = h0 + (r & 15);
        unsigned v = 0;
        if (w < 350 && hc < HS) {
            const bf* src = (arr ? Whh_s : Whh_b) +
                            (((long)dir * 3 + gate) * HS + hc) * (long)HS + 2 * w;
            v = *(const unsigned*)src;
        }
        Wu[(long)arr * 48 * WSTRW + r * WSTRW + w] = v;
    }
    __syncthreads();

    float bq[2][2][3];
#pragma unroll
    for (int nt = 0; nt < 2; nt++)
#pragma unroll
        for (int par = 0; par < 2; par++) {
            int hc = h0 + nt * 8 + tig * 2 + par;
            bool v = hc < HS;
            bq[nt][par][0] = v ? bhh[dir * 3 * HS + hc] : 0.f;
            bq[nt][par][1] = v ? bhh[dir * 3 * HS + HS + hc] : 0.f;
            bq[nt][par][2] = v ? bhh[dir * 3 * HS + 2 * HS + hc] : 0.f;
        }

    for (int s = 0; s < S_LEN; s++) {
        const float* hf_in = (s & 1) ? hfB : hfA;
        const bf*    hb_in = (s & 1) ? hbB : hbA;
        const bf*    hs_in = (s & 1) ? hsB : hsA;
        float* hf_out = (s & 1) ? hfA : hfB;
        bf*    hb_out = (s & 1) ? hbA : hbB;
        bf*    hs_out = (s & 1) ? hsA : hsB;
        int t = dir ? (S_LEN - 1 - s) : s;

        const unsigned* r0b = (const unsigned*)hb_in + ((long)dir * 128 + mrow + gid) * 350;
        const unsigned* r1b = r0b + 8 * 350;
        const unsigned* r0s = (const unsigned*)hs_in + ((long)dir * 128 + mrow + gid) * 350;
        const unsigned* r1s = r0s + 8 * 350;

        float acc[6][4];
#pragma unroll
        for (int nt = 0; nt < 6; nt++)
#pragma unroll
            for (int i = 0; i < 4; i++) acc[nt][i] = 0.f;

        unsigned fa0[8], fa1[8];
        auto loadf = [&](int it, unsigned (&f)[8]) {
            int c0 = it * 8 + tig;
            int c1 = c0 + 4;
            bool g = (c1 < 350);
            f[0] = r0b[c0];           f[1] = r1b[c0];
            f[2] = g ? r0b[c1] : 0u;  f[3] = g ? r1b[c1] : 0u;
            f[4] = r0s[c0];           f[5] = r1s[c0];
            f[6] = g ? r0s[c1] : 0u;  f[7] = g ? r1s[c1] : 0u;
        };
        loadf(0, fa0);
        loadf(1, fa1);

        float xq[2][4][3];
#pragma unroll
        for (int nt = 0; nt < 2; nt++)
#pragma unroll
            for (int i = 0; i < 4; i++) {
                int n = mrow + gid + 8 * (i >> 1);
                int hc = h0 + nt * 8 + tig * 2 + (i & 1);
                bool v = hc < HS;
                long xb = ((long)(dir * S_LEN + t) * 128 + n) * (3 * HS);
                xq[nt][i][0] = v ? xw[xb + hc] : 0.f;
                xq[nt][i][1] = v ? xw[xb + HS + hc] : 0.f;
                xq[nt][i][2] = v ? xw[xb + 2 * HS + hc] : 0.f;
            }

        auto step = [&](int it, unsigned (&f)[8]) {
            unsigned ab[4]  = {f[0], f[1], f[2], f[3]};
            unsigned as_[4] = {f[4], f[5], f[6], f[7]};
            if (it + 2 < 44) loadf(it + 2, f);
            int kb = it * 8;
#pragma unroll
            for (int p = 0; p < 3; p++) {
                unsigned Bb[4], Bs[4];
                unsigned offb = (unsigned)((((p * 16 + lrow) * WSTRW) + kb + lcol4) * 4);
                ldsm4(Bb, wu_sb + offb);
                ldsm4(Bs, wu_sb + (unsigned)(48 * WSTRW * 4) + offb);
#pragma unroll
                for (int sub = 0; sub < 2; sub++) {
                    int nt = 2 * p + sub;
                    mma16(acc[nt], ab,  Bb[sub], Bb[2 + sub]);
                    mma16(acc[nt], ab,  Bs[sub], Bs[2 + sub]);
                    mma16(acc[nt], as_, Bb[sub], Bb[2 + sub]);
                }
            }
        };
        for (int itp = 0; itp < 22; itp++) {
            step(itp * 2,     fa0);
            step(itp * 2 + 1, fa1);
        }

#pragma unroll
        for (int nt = 0; nt < 2; nt++)
#pragma unroll
            for (int i = 0; i < 4; i++) {
                int n = mrow + gid + 8 * (i >> 1);
                int hc = h0 + nt * 8 + tig * 2 + (i & 1);
                if (hc >= HS) continue;
                float gr_ = acc[nt][i]     + bq[nt][i & 1][0];
                float gz_ = acc[nt + 2][i] + bq[nt][i & 1][1];
                float gn_ = acc[nt + 4][i] + bq[nt][i & 1][2];
                float rg = 1.f / (1.f + expf(-(xq[nt][i][0] + gr_)));
                float zg = 1.f / (1.f + expf(-(xq[nt][i][1] + gz_)));
                float ng = tanhf(xq[nt][i][2] + rg * gn_);
                long hidx = ((long)dir * 128 + n) * HS + hc;
                float hp = hf_in[hidx];
                float hn = (1.f - zg) * ng + zg * hp;
                hf_out[hidx] = hn;
                bf hb_, hs_; bsplit(hn, hb_, hs_);
                hb_out[hidx] = hb_;
                hs_out[hidx] = hs_;
                if (y_b) {
                    long yi = ((long)t * 128 + n) * 2 * HS + (long)dir * HS + hc;
                    y_b[yi] = hb_; y_s[yi] = hs_;
                }
            }

        __threadfence();
        __syncthreads();
        if (tid == 0) {
            atomicAdd(&bar[dir], 1u);
            unsigned target = (unsigned)DIRB_S * (s + 1);
            unsigned v;
            const unsigned* bp = &bar[dir];
            while (1) {
                asm volatile("ld.global.cg.u32 %0, [%1];" : "=r"(v) : "l"(bp));
                if (v >= target) break;
                __nanosleep(64);
            }
            __threadfence();
        }
        __syncthreads();
    }
}

/* ---- concat [hf0|hb0|hf1|hb1] rows, split bf16 output ----------------------- */
__global__ void concat4_split(const float* __restrict__ h0f,
                              const float* __restrict__ h1f,
                              bf* __restrict__ ob, bf* __restrict__ os,
                              int Nrows, int H, int KP) {
    long idx = blockIdx.x * 256L + threadIdx.x;
    int C = 4 * H;
    if (idx >= (long)Nrows * C) return;
    int c = (int)(idx % C);
    long n = idx / C;
    float v;
    if (c < 2 * H) {
        int d = c / H, hh = c % H;
        v = h0f[((long)d * Nrows + n) * KP + hh];
    } else {
        int c2 = c - 2 * H;
        int d = c2 / H, hh = c2 % H;
        v = h1f[((long)d * Nrows + n) * KP + hh];
    }
    bf vb, vs; bsplit(v, vb, vs);
    ob[idx] = vb; os[idx] = vs;
}

/* ---- concat fp32 (final output) --------------------------------------------- */
__global__ void concat4_k(const float* __restrict__ h0f, const float* __restrict__ h1f,
                          float* __restrict__ out, int Nrows, int H, int KP) {
    long idx = blockIdx.x * 256L + threadIdx.x;
    int C = 4 * H;
    if (idx >= (long)Nrows * C) return;
    int c = (int)(idx % C);
    long n = idx / C;
    float v;
    if (c < 2 * H) {
        int d = c / H, hh = c % H;
        v = h0f[((long)d * Nrows + n) * KP + hh];
    } else {
        int c2 = c - 2 * H;
        int d = c2 / H, hh = c2 % H;
        v = h1f[((long)d * Nrows + n) * KP + hh];
    }
    out[idx] = v;
}

/* ---------------------------------- host ------------------------------------ */
extern "C" void kernel_launch(void* const* d_in, const int* in_sizes, int n_in,
                              void* d_out, int out_size) {
    const int*   x        = (const int*)  d_in[0];
    const float* emb      = (const float*)d_in[1];
    const float* we_Wih0  = (const float*)d_in[2];
    const float* we_Whh0  = (const float*)d_in[3];
    const float* we_bih0  = (const float*)d_in[4];
    const float* we_bhh0  = (const float*)d_in[5];
    const float* we_Wih1  = (const float*)d_in[6];
    const float* we_Whh1  = (const float*)d_in[7];
    const float* we_bih1  = (const float*)d_in[8];
    const float* we_bhh1  = (const float*)d_in[9];
    const float* se_Wih0  = (const float*)d_in[10];
    const float* se_Whh0  = (const float*)d_in[11];
    const float* se_bih0  = (const float*)d_in[12];
    const float* se_bhh0  = (const float*)d_in[13];
    const float* se_Wih1  = (const float*)d_in[14];
    const float* se_Whh1  = (const float*)d_in[15];
    const float* se_bih1  = (const float*)d_in[16];
    const float* se_bhh1  = (const float*)d_in[17];
    (void)in_sizes; (void)n_in; (void)out_size;

    bf *xe_b, *xe_s, *y0w_b, *y0w_s, *words_b, *words_s, *y0s_b, *y0s_s;
    float *xw, *hwf, *hsf;
    bf *hsb, *hss;
    unsigned* bar;
    bf *wW0b,*wW0s,*wW1b,*wW1s,*wH0b,*wH0s,*wH1b,*wH1s;
    bf *sW0b,*sW0s,*sW1b,*sW1s,*sH0b,*sH0s,*sH1b,*sH1s;
    cudaGetSymbolAddress((void**)&xe_b, g_xe_b);   cudaGetSymbolAddress((void**)&xe_s, g_xe_s);
    cudaGetSymbolAddress((void**)&xw, g_xw);
    cudaGetSymbolAddress((void**)&y0w_b, g_y0w_b); cudaGetSymbolAddress((void**)&y0w_s, g_y0w_s);
    cudaGetSymbolAddress((void**)&words_b, g_words_b); cudaGetSymbolAddress((void**)&words_s, g_words_s);
    cudaGetSymbolAddress((void**)&y0s_b, g_y0s_b); cudaGetSymbolAddress((void**)&y0s_s, g_y0s_s);
    cudaGetSymbolAddress((void**)&hwf, g_hwf);     cudaGetSymbolAddress((void**)&hsf, g_hsf);
    cudaGetSymbolAddress((void**)&hsb, g_hsb);     cudaGetSymbolAddress((void**)&hss, g_hss);
    cudaGetSymbolAddress((void**)&bar, g_bar);
    cudaGetSymbolAddress((void**)&wW0b, g_weWih0_b); cudaGetSymbolAddress((void**)&wW0s, g_weWih0_s);
    cudaGetSymbolAddress((void**)&wW1b, g_weWih1_b); cudaGetSymbolAddress((void**)&wW1s, g_weWih1_s);
    cudaGetSymbolAddress((void**)&wH0b, g_weWhh0_b); cudaGetSymbolAddress((void**)&wH0s, g_weWhh0_s);
    cudaGetSymbolAddress((void**)&wH1b, g_weWhh1_b); cudaGetSymbolAddress((void**)&wH1s, g_weWhh1_s);
    cudaGetSymbolAddress((void**)&sW0b, g_seWih0_b); cudaGetSymbolAddress((void**)&sW0s, g_seWih0_s);
    cudaGetSymbolAddress((void**)&sW1b, g_seWih1_b); cudaGetSymbolAddress((void**)&sW1s, g_seWih1_s);
    cudaGetSymbolAddress((void**)&sH0b, g_seWhh0_b); cudaGetSymbolAddress((void**)&sH0s, g_seWhh0_s);
    cudaGetSymbolAddress((void**)&sH1b, g_seWhh1_b); cudaGetSymbolAddress((void**)&sH1s, g_seWhh1_s);

    cudaFuncSetAttribute(gru_sent_persistent,
                         cudaFuncAttributeMaxDynamicSharedMemorySize, SMEM_PERS);
    cudaFuncSetAttribute(gru_word_persistent,
                         cudaFuncAttributeMaxDynamicSharedMemorySize, WORD_SMEM);
    cudaFuncSetAttribute(mma_gemm_bias,
                         cudaFuncAttributeMaxDynamicSharedMemorySize, GEMM_SMEM);

    float* hwF[2];
    float* hsF[4]; bf* hsB[4]; bf* hsS[4];
    hwF[0] = hwf; hwF[1] = hwf + (long)HWBUF_N;
    for (int i = 0; i < 4; i++) {
        hsF[i] = hsf + (long)i * HSBUF_N;
        hsB[i] = hsb + (long)i * HSBUF_N;
        hsS[i] = hss + (long)i * HSBUF_N;
    }

    /* 0. split all weights in one launch */
    split_all<<<(unsigned)((SPLIT_TOTAL + 255) / 256), 256>>>(
        we_Wih0, wW0b, wW0s, we_Wih1, wW1b, wW1s,
        we_Whh0, wH0b, wH0s, we_Whh1, wH1b, wH1s,
        se_Wih0, sW0b, sW0s, se_Wih1, sW1b, sW1s,
        se_Whh0, sH0b, sH0s, se_Whh1, sH1b, sH1s);

    /* 1. embedding (split) */
    embed_split_k<<<(XE_N + 255) / 256, 256>>>(x, emb, xe_b, xe_s);

    /* 2. word layer0: xw precompute + register-resident recurrence */
    for (int d = 0; d < 2; d++) {
        dim3 g((3 * HW + 127) / 128, (T_LEN * NW) / 128);
        mma_gemm_bias<<<g, 256, GEMM_SMEM>>>(xe_b, xe_s,
                                  wW0b + (long)d * 3 * HW * E_DIM,
                                  wW0s + (long)d * 3 * HW * E_DIM,
                                  we_bih0 + d * 3 * HW,
                                  xw + (long)d * T_LEN * NW * 3 * HW,
                                  T_LEN * NW, 3 * HW, E_DIM);
    }
    gru_word_persistent<<<480, 128, WORD_SMEM>>>(hwF[0], xw, wH0b, wH0s,
                                                 we_bhh0, y0w_b, y0w_s);

    /* 3. word layer1 */
    for (int d = 0; d < 2; d++) {
        dim3 g((3 * HW + 127) / 128, (T_LEN * NW) / 128);
        mma_gemm_bias<<<g, 256, GEMM_SMEM>>>(y0w_b, y0w_s,
                                  wW1b + (long)d * 3 * HW * 2 * HW,
                                  wW1s + (long)d * 3 * HW * 2 * HW,
                                  we_bih1 + d * 3 * HW,
                                  xw + (long)d * T_LEN * NW * 3 * HW,
                                  T_LEN * NW, 3 * HW, 2 * HW);
    }
    gru_word_persistent<<<480, 128, WORD_SMEM>>>(hwF[1], xw, wH1b, wH1s,
                                                 we_bhh1, (bf*)0, (bf*)0);

    /* 4. words = [hf0|hb0|hf1|hb1] split : [NW, 300] */
    concat4_split<<<(WORDS_N + 255) / 256, 256>>>(hwF[0], hwF[1],
                                                  words_b, words_s, NW, HW, HWP);

    /* 5. sentence layer0: xw precompute + persistent recurrence */
    for (int d = 0; d < 2; d++) {
        dim3 g((3 * HS + 127) / 128, (S_LEN * B_SZ) / 128);
        mma_gemm_bias<<<g, 256, GEMM_SMEM>>>(words_b, words_s,
                                  sW0b + (long)d * 3 * HS * 4 * HW,
                                  sW0s + (long)d * 3 * HS * 4 * HW,
                                  se_bih0 + d * 3 * HS,
                                  xw + (long)d * S_LEN * B_SZ * 3 * HS,
                                  S_LEN * B_SZ, 3 * HS, 4 * HW);
    }
    cudaMemsetAsync(hsF[0], 0, sizeof(float) * HSBUF_N);
    cudaMemsetAsync(hsB[0], 0, sizeof(bf) * HSBUF_N);
    cudaMemsetAsync(hsS[0], 0, sizeof(bf) * HSBUF_N);
    cudaMemsetAsync(bar, 0, 2 * sizeof(unsigned));
    gru_sent_persistent<<<NBLK_S, 256, SMEM_PERS>>>(
        sH0b, sH0s, se_bhh0, xw,
        hsF[0], hsB[0], hsS[0], hsF[1], hsB[1], hsS[1],
        y0s_b, y0s_s, bar);

    /* 6. sentence layer1 */
    for (int d = 0; d < 2; d++) {
        dim3 g((3 * HS + 127) / 128, (S_LEN * B_SZ) / 128);
        mma_gemm_bias<<<g, 256, GEMM_SMEM>>>(y0s_b, y0s_s,
                                  sW1b + (long)d * 3 * HS * 2 * HS,
                                  sW1s + (long)d * 3 * HS * 2 * HS,
                                  se_bih1 + d * 3 * HS,
                                  xw + (long)d * S_LEN * B_SZ * 3 * HS,
                                  S_LEN * B_SZ, 3 * HS, 2 * HS);
    }
    cudaMemsetAsync(hsF[2], 0, sizeof(float) * HSBUF_N);
    cudaMemsetAsync(hsB[2], 0, sizeof(bf) * HSBUF_N);
    cudaMemsetAsync(hsS[2], 0, sizeof(bf) * HSBUF_N);
    cudaMemsetAsync(bar, 0, 2 * sizeof(unsigned));
    gru_sent_persistent<<<NBLK_S, 256, SMEM_PERS>>>(
        sH1b, sH1s, se_bhh1, xw,
        hsF[2], hsB[2], hsS[2], hsF[3], hsB[3], hsS[3],
        (bf*)0, (bf*)0, bar);

    /* 7. output [1, 128, 2800] = [sf0|sb0|sf1|sb1] per batch row */
    concat4_k<<<((long)B_SZ * 4 * HS + 255) / 256, 256>>>(hsF[0], hsF[2],
                                                          (float*)d_out,
                                                          B_SZ, HS, HS);
}

// round 15
// speedup vs baseline: 1.0796x; 1.0796x over previous
#include <cuda_runtime.h>
#include <cuda_bf16.h>
#include <math.h>

#define S_LEN 120
#define T_LEN 10
#define B_SZ  128
#define E_DIM 80
#define HW    75
#define HWP   76
#define HW2P  152             /* padded 2*HW for 16B rows */
#define W4P   304             /* padded 4*HW for 16B rows */
#define HS    700
#define NW    (S_LEN * B_SZ)   /* 15360 word-level batch */

typedef __nv_bfloat16 bf;

#define XE_N    (T_LEN * NW * E_DIM)
#define XW_N    (2L * T_LEN * NW * (3 * HW))
#define Y0W_N   (T_LEN * NW * HW2P)
#define WORDS_N (NW * W4P)
#define Y0S_N   ((long)S_LEN * B_SZ * 2 * HS)
#define HWBUF_N (2 * NW * HWP)
#define HSBUF_N (2 * B_SZ * HS)

#define NBLK_S  88            /* sentence persistent: 2 dirs x 44 hc tiles of 16 */
#define DIRB_S  44
#define WSTRW   356           /* u32 stride of sentence W smem row */
#define SMEM_PERS (2 * 48 * WSTRW * 4)       /* 136704 B */

#define WQ      41            /* u32 stride of word W smem row */
#define WORD_SMEM (2 * 240 * WQ * 4)         /* 78720 B */

#define GSTR    40            /* bf stride of GEMM smem row (80B, 16B aligned) */
#define GEMM_SMEM (2 * 4 * 128 * GSTR * 2)   /* 81920 B */

/* ---------------- persistent scratch (device globals; no allocs) ------------- */
__device__ bf    g_xe_b[XE_N],    g_xe_s[XE_N];
__device__ float g_xw[XW_N];
__device__ bf    g_y0w_b[Y0W_N],  g_y0w_s[Y0W_N];      /* pad cols 150-151 stay 0 */
__device__ bf    g_words_b[WORDS_N], g_words_s[WORDS_N]; /* pad cols 300-303 stay 0 */
__device__ bf    g_y0s_b[Y0S_N],  g_y0s_s[Y0S_N];
__device__ float g_hwf[2][HWBUF_N];
__device__ float g_hsf[4][HSBUF_N];
__device__ bf    g_hsb[4][HSBUF_N], g_hss[4][HSBUF_N];
__device__ unsigned g_bar[2];
/* weight splits */
__device__ bf g_weWih0_b[2*3*HW*E_DIM],  g_weWih0_s[2*3*HW*E_DIM];
__device__ bf g_weWih1_b[2*3*HW*HW2P],   g_weWih1_s[2*3*HW*HW2P];
__device__ bf g_weWhh0_b[2*3*HW*HWP],    g_weWhh0_s[2*3*HW*HWP];
__device__ bf g_weWhh1_b[2*3*HW*HWP],    g_weWhh1_s[2*3*HW*HWP];
__device__ bf g_seWih0_b[2*3*HS*W4P],    g_seWih0_s[2*3*HS*W4P];
__device__ bf g_seWih1_b[2*3*HS*2*HS],   g_seWih1_s[2*3*HS*2*HS];
__device__ bf g_seWhh0_b[2*3*HS*HS],     g_seWhh0_s[2*3*HS*HS];
__device__ bf g_seWhh1_b[2*3*HS*HS],     g_seWhh1_s[2*3*HS*HS];

/* ---------------- helpers ---------------------------------------------------- */
__device__ __forceinline__ void bsplit(float v, bf &b, bf &s) {
    b = __float2bfloat16_rn(v);
    s = __float2bfloat16_rn(v - __bfloat162float(b));
}
__device__ __forceinline__ void mma16(float d[4], const unsigned a[4],
                                      unsigned b0, unsigned b1) {
    asm volatile(
        "mma.sync.aligned.m16n8k16.row.col.f32.bf16.bf16.f32 "
        "{%0,%1,%2,%3},{%4,%5,%6,%7},{%8,%9},{%0,%1,%2,%3};"
        : "+f"(d[0]), "+f"(d[1]), "+f"(d[2]), "+f"(d[3])
        : "r"(a[0]), "r"(a[1]), "r"(a[2]), "r"(a[3]), "r"(b0), "r"(b1));
}
__device__ __forceinline__ void ldsm4(unsigned (&r)[4], unsigned addr) {
    asm volatile("ldmatrix.sync.aligned.m8n8.x4.shared.b16 {%0,%1,%2,%3}, [%4];"
        : "=r"(r[0]), "=r"(r[1]), "=r"(r[2]), "=r"(r[3]) : "r"(addr));
}
__device__ __forceinline__ void cpasync16(unsigned saddr, const void* g, bool p) {
    asm volatile("cp.async.cg.shared.global [%0], [%1], 16, %2;"
                 :: "r"(saddr), "l"(g), "r"(p ? 16u : 0u));
}
__device__ __forceinline__ void cp_commit() { asm volatile("cp.async.commit_group;"); }
__device__ __forceinline__ void cp_wait1()  { asm volatile("cp.async.wait_group 1;"); }
__device__ __forceinline__ void cp_wait0()  { asm volatile("cp.async.wait_group 0;"); }

/* ---------------- merged weight split (all 8 tensors, one launch) ------------- */
__device__ __forceinline__ void do_split(const float* W, bf* b, bf* s,
                                         long rel, int K, int KP) {
    int k = (int)(rel % KP);
    long r = rel / KP;
    float v = (k < K) ? W[r * K + k] : 0.f;
    bf vb, vs; bsplit(v, vb, vs);
    b[rel] = vb; s[rel] = vs;
}
__global__ void split_all(
    const float* W0, bf* b0, bf* s0, const float* W1, bf* b1, bf* s1,
    const float* W2, bf* b2, bf* s2, const float* W3, bf* b3, bf* s3,
    const float* W4, bf* b4, bf* s4, const float* W5, bf* b5, bf* s5,
    const float* W6, bf* b6, bf* s6, const float* W7, bf* b7, bf* s7)
{
    const long N0 = 450L*80,   C0 = N0;
    const long N1 = 450L*HW2P, C1 = C0 + N1;
    const long N2 = 450L*76,   C2 = C1 + N2;
    const long N3 = 450L*76,   C3 = C2 + N3;
    const long N4 = 4200L*W4P,  C4 = C3 + N4;
    const long N5 = 4200L*1400, C5 = C4 + N5;
    const long N6 = 4200L*700,  C6 = C5 + N6;
    const long N7 = 4200L*700,  C7 = C6 + N7;
    long idx = blockIdx.x * 256L + threadIdx.x;
    if (idx >= C7) return;
    if      (idx < C0) do_split(W0, b0, s0, idx,        80,   80);
    else if (idx < C1) do_split(W1, b1, s1, idx - C0,   150,  HW2P);
    else if (idx < C2) do_split(W2, b2, s2, idx - C1,   75,   76);
    else if (idx < C3) do_split(W3, b3, s3, idx - C2,   75,   76);
    else if (idx < C4) do_split(W4, b4, s4, idx - C3,   300,  W4P);
    else if (idx < C5) do_split(W5, b5, s5, idx - C4,   1400, 1400);
    else if (idx < C6) do_split(W6, b6, s6, idx - C5,   700,  700);
    else               do_split(W7, b7, s7, idx - C6,   700,  700);
}
#define SPLIT_TOTAL (450L*80 + 450L*HW2P + 450L*76 + 450L*76 + 4200L*W4P + 4200L*1400 + 4200L*700 + 4200L*700)

/* ---------------- embedding gather + split ----------------------------------- */
__global__ void embed_split_k(const int* __restrict__ x, const float* __restrict__ emb,
                              bf* __restrict__ xb, bf* __restrict__ xs) {
    long idx = blockIdx.x * 256L + threadIdx.x;
    if (idx >= XE_N) return;
    int e = (int)(idx % E_DIM);
    int n = (int)((idx / E_DIM) % NW);
    int t = (int)(idx / ((long)E_DIM * NW));
    int s = n >> 7, bb_ = n & 127;
    int tok = x[(s * T_LEN + t) * B_SZ + bb_];
    float v = emb[(long)tok * E_DIM + e];
    bf vb, vs; bsplit(v, vb, vs);
    xb[idx] = vb; xs[idx] = vs;
}

/* -------- C[m][g] = bias[g] + A[m,:]·W[g,:]  (split A & W, 3-mma) ------------
   Tile 128x128, BK=32 bf. 16B cp.async fill (K mult of 8, rows 16B-aligned),
   LDSM fragment loads. -------------------------------------------------------- */
__global__ __launch_bounds__(256) void mma_gemm_bias(
    const bf* __restrict__ Ab_g, const bf* __restrict__ As_g,
    const bf* __restrict__ Wb_g, const bf* __restrict__ Ws_g,
    const float* __restrict__ bias, float* __restrict__ C,
    int M, int G, int K)
{
    extern __shared__ __align__(16) bf gsm[];   /* [2 buf][4 arr][128][GSTR] */
    unsigned sbase = (unsigned)__cvta_generic_to_shared(gsm);
    int tid = threadIdx.x, lane = tid & 31, wid = tid >> 5;
    int gid = lane >> 2, tig = lane & 3;
    int wm = wid & 3, wn = wid >> 2;
    int row0 = blockIdx.y * 128, col0 = blockIdx.x * 128;
    int lrow = lane & 15, lcol8 = (lane >> 4) << 3;

    float acc[2][8][4];
#pragma unroll
    for (int mt = 0; mt < 2; mt++)
#pragma unroll
        for (int nt = 0; nt < 8; nt++)
#pragma unroll
            for (int i = 0; i < 4; i++) acc[mt][nt][i] = 0.f;

    auto fill = [&](int buf, int k0) {
#pragma unroll
        for (int j = 0; j < 8; j++) {
            int e = j * 256 + tid;        /* 0..2047 16B chunks */
            int arr = e >> 9;             /* 512 chunks per array */
            int rem = e & 511;
            int row = rem >> 2, c16 = rem & 3;
            int gk = k0 + c16 * 8;
            unsigned sa = sbase + (unsigned)(((buf * 4 + arr) * 128 + row) * GSTR * 2 + c16 * 16);
            const bf* gp; bool v;
            if (arr < 2) {
                v = (gk < K) && (row0 + row < M);
                gp = (arr ? As_g : Ab_g) + (v ? ((long)(row0 + row) * K + gk) : 0);
            } else {
                int gc = col0 + row;
                v = (gk < K) && (gc < G);
                gp = (arr == 2 ? Wb_g : Ws_g) + (v ? ((long)gc * K + gk) : 0);
            }
            cpasync16(sa, gp, v);
        }
        cp_commit();
    };

    fill(0, 0);
    int buf = 0;
    for (int k0 = 0; k0 < K; k0 += 32) {
        bool more = (k0 + 32 < K);
        if (more) fill(1 - buf, k0 + 32);
        if (more) cp_wait1(); else cp_wait0();
        __syncthreads();

        unsigned base0 = sbase + (unsigned)(2 * (buf * 4) * 128 * GSTR);
        unsigned arrStride = (unsigned)(2 * 128 * GSTR);
#pragma unroll
        for (int kc = 0; kc < 32; kc += 16) {
            unsigned Ab[2][4], As[2][4];
#pragma unroll
            for (int mt = 0; mt < 2; mt++) {
                int row = wm * 32 + mt * 16 + lrow;
                unsigned off = (unsigned)((row * GSTR + kc + lcol8) * 2);
                ldsm4(Ab[mt], base0 + off);
                ldsm4(As[mt], base0 + arrStride + off);
            }
#pragma unroll
            for (int p = 0; p < 4; p++) {
                int row = wn * 64 + p * 16 + lrow;
                unsigned off = (unsigned)((row * GSTR + kc + lcol8) * 2);
                unsigned Bb[4], Bs[4];
                ldsm4(Bb, base0 + 2 * arrStride + off);
                ldsm4(Bs, base0 + 3 * arrStride + off);
#pragma unroll
                for (int sub = 0; sub < 2; sub++) {
                    int nt = 2 * p + sub;
                    unsigned bb0 = Bb[sub], bb1 = Bb[2 + sub];
                    unsigned bs0 = Bs[sub], bs1 = Bs[2 + sub];
#pragma unroll
                    for (int mt = 0; mt < 2; mt++) {
                        mma16(acc[mt][nt], Ab[mt], bb0, bb1);
                        mma16(acc[mt][nt], Ab[mt], bs0, bs1);
                        mma16(acc[mt][nt], As[mt], bb0, bb1);
                    }
                }
            }
        }
        __syncthreads();
        buf = 1 - buf;
    }
#pragma unroll
    for (int mt = 0; mt < 2; mt++)
#pragma unroll
        for (int nt = 0; nt < 8; nt++)
#pragma unroll
            for (int i = 0; i < 4; i++) {
                int gr = row0 + wm * 32 + mt * 16 + gid + 8 * (i >> 1);
                int gc = col0 + wn * 64 + nt * 8 + tig * 2 + (i & 1);
                if (gr < M && gc < G)
                    C[(long)gr * G + gc] = acc[mt][nt][i] + bias[gc];
            }
}

/* -------- word GRU: register-resident h across ALL 10 timesteps -------------- */
__global__ __launch_bounds__(128) void gru_word_persistent(
    float* __restrict__ hf_out,
    const float* __restrict__ xw,
    const bf* __restrict__ Whh_b, const bf* __restrict__ Whh_s,
    const float* __restrict__ bhh,
    bf* __restrict__ y_b, bf* __restrict__ y_s)
{
    extern __shared__ __align__(16) unsigned Wsm[];   /* [2][240][WQ] */
    int tid = threadIdx.x, lane = tid & 31, wid = tid >> 5;
    int gid = lane >> 2, tig = lane & 3;
    int dir = blockIdx.x / 240;
    int n0 = (blockIdx.x % 240) * 64;
    int mrow = wid * 16;

    for (int e = tid; e < 2 * 240 * WQ; e += 128) {
        int arr = e / (240 * WQ);
        int rem = e % (240 * WQ);
        int r = rem / WQ, w = rem % WQ;
        int gate = r / 80, hcl = r % 80;
        unsigned v = 0;
        if (hcl < 75 && w < 38) {
            const bf* src = (arr ? Whh_s : Whh_b) +
                            ((long)(dir * 3 + gate) * 75 + hcl) * HWP + 2 * w;
            v = *(const unsigned*)src;
        }
        Wsm[(arr * 240 + r) * WQ + w] = v;
    }
    __syncthreads();

    unsigned hbf[5][4], hsf[5][4];
    float hpf[5][4][2];
#pragma unroll
    for (int kt = 0; kt < 5; kt++)
#pragma unroll
        for (int j = 0; j < 4; j++) {
            hbf[kt][j] = 0u; hsf[kt][j] = 0u;
            hpf[kt][j][0] = 0.f; hpf[kt][j][1] = 0.f;
        }

    for (int s = 0; s < T_LEN; s++) {
        int t = dir ? (T_LEN - 1 - s) : s;
        unsigned nhb[5][4], nhs[5][4];
#pragma unroll
        for (int ntg = 0; ntg < 10; ntg++) {
            float ar[4] = {0.f,0.f,0.f,0.f};
            float az[4] = {0.f,0.f,0.f,0.f};
            float an[4] = {0.f,0.f,0.f,0.f};
#pragma unroll
            for (int kt = 0; kt < 5; kt++) {
                int cr = ntg * 8 + gid;
                int ko = kt * 8 + tig;
                unsigned rb0 = Wsm[(0 * 240 + cr) * WQ + ko];
                unsigned rb1 = Wsm[(0 * 240 + cr) * WQ + ko + 4];
                unsigned rs0 = Wsm[(1 * 240 + cr) * WQ + ko];
                unsigned rs1 = Wsm[(1 * 240 + cr) * WQ + ko + 4];
                unsigned zb0 = Wsm[(0 * 240 + 80 + cr) * WQ + ko];
                unsigned zb1 = Wsm[(0 * 240 + 80 + cr) * WQ + ko + 4];
                unsigned zs0 = Wsm[(1 * 240 + 80 + cr) * WQ + ko];
                unsigned zs1 = Wsm[(1 * 240 + 80 + cr) * WQ + ko + 4];
                unsigned nb0 = Wsm[(0 * 240 + 160 + cr) * WQ + ko];
                unsigned nb1 = Wsm[(0 * 240 + 160 + cr) * WQ + ko + 4];
                unsigned ns0 = Wsm[(1 * 240 + 160 + cr) * WQ + ko];
                unsigned ns1 = Wsm[(1 * 240 + 160 + cr) * WQ + ko + 4];
                mma16(ar, hbf[kt], rb0, rb1);
                mma16(ar, hbf[kt], rs0, rs1);
                mma16(ar, hsf[kt], rb0, rb1);
                mma16(az, hbf[kt], zb0, zb1);
                mma16(az, hbf[kt], zs0, zs1);
                mma16(az, hsf[kt], zb0, zb1);
                mma16(an, hbf[kt], nb0, nb1);
                mma16(an, hbf[kt], ns0, ns1);
                mma16(an, hsf[kt], nb0, nb1);
            }
            int kt_e = ntg >> 1, half = ntg & 1;
#pragma unroll
            for (int ii = 0; ii < 2; ii++) {
                int n = n0 + mrow + gid + 8 * ii;
                int j = 2 * half + ii;
                unsigned hb2 = 0u, hs2 = 0u;
#pragma unroll
                for (int par = 0; par < 2; par++) {
                    int hc = ntg * 8 + tig * 2 + par;
                    float hn = 0.f;
                    bf b_ = __float2bfloat16_rn(0.f), s_ = b_;
                    if (hc < 75) {
                        float hp = hpf[kt_e][j][par];
                        long xb = ((long)(dir * T_LEN + t) * NW + n) * 225;
                        float xr = xw[xb + hc];
                        float xz = xw[xb + 75 + hc];
                        float xn = xw[xb + 150 + hc];
                        float gr_ = ar[ii * 2 + par] + bhh[dir * 225 + hc];
                        float gz_ = az[ii * 2 + par] + bhh[dir * 225 + 75 + hc];
                        float gn_ = an[ii * 2 + par] + bhh[dir * 225 + 150 + hc];
                        float rg = 1.f / (1.f + expf(-(xr + gr_)));
                        float zg = 1.f / (1.f + expf(-(xz + gz_)));
                        float ng = tanhf(xn + rg * gn_);
                        hn = (1.f - zg) * ng + zg * hp;
                        bsplit(hn, b_, s_);
                        if (y_b) {
                            long yi = ((long)t * NW + n) * HW2P + (long)dir * 75 + hc;
                            y_b[yi] = b_; y_s[yi] = s_;
                        }
                    }
                    hpf[kt_e][j][par] = hn;
                    hb2 |= (unsigned)__bfloat16_as_ushort(b_) << (16 * par);
                    hs2 |= (unsigned)__bfloat16_as_ushort(s_) << (16 * par);
                }
                nhb[kt_e][j] = hb2;
                nhs[kt_e][j] = hs2;
            }
        }
#pragma unroll
        for (int kt = 0; kt < 5; kt++)
#pragma unroll
            for (int j = 0; j < 4; j++) {
                hbf[kt][j] = nhb[kt][j];
                hsf[kt][j] = nhs[kt][j];
            }
    }

#pragma unroll
    for (int kt = 0; kt < 5; kt++)
#pragma unroll
        for (int j = 0; j < 4; j++)
#pragma unroll
            for (int par = 0; par < 2; par++) {
                int n = n0 + mrow + gid + 8 * (j & 1);
                int hc = kt * 16 + (j >> 1) * 8 + tig * 2 + par;
                if (hc < 75)
                    hf_out[((long)dir * NW + n) * HWP + hc] = hpf[kt][j][par];
            }
}

/* -------- persistent sentence GRU (round-12 proven shape): 88 blocks, Whh in
   SMEM (scalar LDS), direct global h fragments, depth-2 prefetch, hoisted
   bias/xw, per-dir barriers. -------------------------------------------------- */
__global__ __launch_bounds__(256) void gru_sent_persistent(
    const bf* __restrict__ Whh_b, const bf* __restrict__ Whh_s,
    const float* __restrict__ bhh, const float* __restrict__ xw,
    float* __restrict__ hfA, bf* __restrict__ hbA, bf* __restrict__ hsA,
    float* __restrict__ hfB, bf* __restrict__ hbB, bf* __restrict__ hsB,
    bf* __restrict__ y_b, bf* __restrict__ y_s, unsigned* __restrict__ bar)
{
    extern __shared__ __align__(16) unsigned smem_u[];
    unsigned* Wu = smem_u;                       /* [2][48][WSTRW] */

    int tid = threadIdx.x, lane = tid & 31, wid = tid >> 5;
    int gid = lane >> 2, tig = lane & 3;
    int dir = blockIdx.x / DIRB_S;
    int h0 = (blockIdx.x % DIRB_S) * 16;
    int mrow = wid * 16;

    for (int e = tid; e < 2 * 48 * 352; e += 256) {
        int arr = e / (48 * 352);
        int rem = e % (48 * 352);
        int r = rem / 352, w = rem % 352;
        int gate = r >> 4, hc = h0 + (r & 15);
        unsigned v = 0;
        if (w < 350 && hc < HS) {
            const bf* src = (arr ? Whh_s : Whh_b) +
                            (((long)dir * 3 + gate) * HS + hc) * (long)HS + 2 * w;
            v = *(const unsigned*)src;
        }
        Wu[(long)arr * 48 * WSTRW + r * WSTRW + w] = v;
    }
    __syncthreads();

    float bq[2][2][3];
#pragma unroll
    for (int nt = 0; nt < 2; nt++)
#pragma unroll
        for (int par = 0; par < 2; par++) {
            int hc = h0 + nt * 8 + tig * 2 + par;
            bool v = hc < HS;
            bq[nt][par][0] = v ? bhh[dir * 3 * HS + hc] : 0.f;
            bq[nt][par][1] = v ? bhh[dir * 3 * HS + HS + hc] : 0.f;
            bq[nt][par][2] = v ? bhh[dir * 3 * HS + 2 * HS + hc] : 0.f;
        }

    for (int s = 0; s < S_LEN; s++) {
        const float* hf_in = (s & 1) ? hfB : hfA;
        const bf*    hb_in = (s & 1) ? hbB : hbA;
        const bf*    hs_in = (s & 1) ? hsB : hsA;
        float* hf_out = (s & 1) ? hfA : hfB;
        bf*    hb_out = (s & 1) ? hbA : hbB;
        bf*    hs_out = (s & 1) ? hsA : hsB;
        int t = dir ? (S_LEN - 1 - s) : s;

        const unsigned* r0b = (const unsigned*)hb_in + ((long)dir * 128 + mrow + gid) * 350;
        const unsigned* r1b = r0b + 8 * 350;
        const unsigned* r0s = (const unsigned*)hs_in + ((long)dir * 128 + mrow + gid) * 350;
        const unsigned* r1s = r0s + 8 * 350;

        float acc[6][4];
#pragma unroll
        for (int nt = 0; nt < 6; nt++)
#pragma unroll
            for (int i = 0; i < 4; i++) acc[nt][i] = 0.f;

        unsigned fa0[8], fa1[8];
        auto loadf = [&](int it, unsigned (&f)[8]) {
            int c0 = it * 8 + tig;
            int c1 = c0 + 4;
            bool g = (c1 < 350);
            f[0] = r0b[c0];           f[1] = r1b[c0];
            f[2] = g ? r0b[c1] : 0u;  f[3] = g ? r1b[c1] : 0u;
            f[4] = r0s[c0];           f[5] = r1s[c0];
            f[6] = g ? r0s[c1] : 0u;  f[7] = g ? r1s[c1] : 0u;
        };
        loadf(0, fa0);
        loadf(1, fa1);

        float xq[2][4][3];
#pragma unroll
        for (int nt = 0; nt < 2; nt++)
#pragma unroll
            for (int i = 0; i < 4; i++) {
                int n = mrow + gid + 8 * (i >> 1);
                int hc = h0 + nt * 8 + tig * 2 + (i & 1);
                bool v = hc < HS;
                long xb = ((long)(dir * S_LEN + t) * 128 + n) * (3 * HS);
                xq[nt][i][0] = v ? xw[xb + hc] : 0.f;
                xq[nt][i][1] = v ? xw[xb + HS + hc] : 0.f;
                xq[nt][i][2] = v ? xw[xb + 2 * HS + hc] : 0.f;
            }

        auto step = [&](int it, unsigned (&f)[8]) {
            unsigned ab[4]  = {f[0], f[1], f[2], f[3]};
            unsigned as_[4] = {f[4], f[5], f[6], f[7]};
            if (it + 2 < 44) loadf(it + 2, f);
            int kb = it * 8;
#pragma unroll
            for (int nt = 0; nt < 6; nt++) {
                const unsigned* pb = Wu + (nt * 8 + gid) * WSTRW + kb;
                const unsigned* ps = pb + 48 * WSTRW;
                unsigned bb0 = pb[tig], bb1 = pb[tig + 4];
                unsigned bs0 = ps[tig], bs1 = ps[tig + 4];
                mma16(acc[nt], ab, bb0, bb1);
                mma16(acc[nt], ab, bs0, bs1);
                mma16(acc[nt], as_, bb0, bb1);
            }
        };
        for (int itp = 0; itp < 22; itp++) {
            step(itp * 2,     fa0);
            step(itp * 2 + 1, fa1);
        }

#pragma unroll
        for (int nt = 0; nt < 2; nt++)
#pragma unroll
            for (int i = 0; i < 4; i++) {
                int n = mrow + gid + 8 * (i >> 1);
                int hc = h0 + nt * 8 + tig * 2 + (i & 1);
                if (hc >= HS) continue;
                float gr_ = acc[nt][i]     + bq[nt][i & 1][0];
                float gz_ = acc[nt + 2][i] + bq[nt][i & 1][1];
                float gn_ = acc[nt + 4][i] + bq[nt][i & 1][2];
                float rg = 1.f / (1.f + expf(-(xq[nt][i][0] + gr_)));
                float zg = 1.f / (1.f + expf(-(xq[nt][i][1] + gz_)));
                float ng = tanhf(xq[nt][i][2] + rg * gn_);
                long hidx = ((long)dir * 128 + n) * HS + hc;
                float hp = hf_in[hidx];
                float hn = (1.f - zg) * ng + zg * hp;
                hf_out[hidx] = hn;
                bf hb_, hs_; bsplit(hn, hb_, hs_);
                hb_out[hidx] = hb_;
                hs_out[hidx] = hs_;
                if (y_b) {
                    long yi = ((long)t * 128 + n) * 2 * HS + (long)dir * HS + hc;
                    y_b[yi] = hb_; y_s[yi] = hs_;
                }
            }

        __threadfence();
        __syncthreads();
        if (tid == 0) {
            atomicAdd(&bar[dir], 1u);
            unsigned target = (unsigned)DIRB_S * (s + 1);
            unsigned v;
            const unsigned* bp = &bar[dir];
            while (1) {
                asm volatile("ld.global.cg.u32 %0, [%1];" : "=r"(v) : "l"(bp));
                if (v >= target) break;
                __nanosleep(64);
            }
            __threadfence();
        }
        __syncthreads();
    }
}

/* ---- concat [hf0|hb0|hf1|hb1] rows, split bf16 output (row stride KPout) ---- */
__global__ void concat4_split(const float* __restrict__ h0f,
                              const float* __restrict__ h1f,
                              bf* __restrict__ ob, bf* __restrict__ os,
                              int Nrows, int H, int KP, int KPout) {
    long idx = blockIdx.x * 256L + threadIdx.x;
    int C = 4 * H;
    if (idx >= (long)Nrows * C) return;
    int c = (int)(idx % C);
    long n = idx / C;
    float v;
    if (c < 2 * H) {
        int d = c / H, hh = c % H;
        v = h0f[((long)d * Nrows + n) * KP + hh];
    } else {
        int c2 = c - 2 * H;
        int d = c2 / H, hh = c2 % H;
        v = h1f[((long)d * Nrows + n) * KP + hh];
    }
    bf vb, vs; bsplit(v, vb, vs);
    long o = n * KPout + c;
    ob[o] = vb; os[o] = vs;
}

/* ---- concat fp32 (final output) --------------------------------------------- */
__global__ void concat4_k(const float* __restrict__ h0f, const float* __restrict__ h1f,
                          float* __restrict__ out, int Nrows, int H, int KP) {
    long idx = blockIdx.x * 256L + threadIdx.x;
    int C = 4 * H;
    if (idx >= (long)Nrows * C) return;
    int c = (int)(idx % C);
    long n = idx / C;
    float v;
    if (c < 2 * H) {
        int d = c / H, hh = c % H;
        v = h0f[((long)d * Nrows + n) * KP + hh];
    } else {
        int c2 = c - 2 * H;
        int d = c2 / H, hh = c2 % H;
        v = h1f[((long)d * Nrows + n) * KP + hh];
    }
    out[idx] = v;
}

/* ---------------------------------- host ------------------------------------ */
extern "C" void kernel_launch(void* const* d_in, const int* in_sizes, int n_in,
                              void* d_out, int out_size) {
    const int*   x        = (const int*)  d_in[0];
    const float* emb      = (const float*)d_in[1];
    const float* we_Wih0  = (const float*)d_in[2];
    const float* we_Whh0  = (const float*)d_in[3];
    const float* we_bih0  = (const float*)d_in[4];
    const float* we_bhh0  = (const float*)d_in[5];
    const float* we_Wih1  = (const float*)d_in[6];
    const float* we_Whh1  = (const float*)d_in[7];
    const float* we_bih1  = (const float*)d_in[8];
    const float* we_bhh1  = (const float*)d_in[9];
    const float* se_Wih0  = (const float*)d_in[10];
    const float* se_Whh0  = (const float*)d_in[11];
    const float* se_bih0  = (const float*)d_in[12];
    const float* se_bhh0  = (const float*)d_in[13];
    const float* se_Wih1  = (const float*)d_in[14];
    const float* se_Whh1  = (const float*)d_in[15];
    const float* se_bih1  = (const float*)d_in[16];
    const float* se_bhh1  = (const float*)d_in[17];
    (void)in_sizes; (void)n_in; (void)out_size;

    bf *xe_b, *xe_s, *y0w_b, *y0w_s, *words_b, *words_s, *y0s_b, *y0s_s;
    float *xw, *hwf, *hsf;
    bf *hsb, *hss;
    unsigned* bar;
    bf *wW0b,*wW0s,*wW1b,*wW1s,*wH0b,*wH0s,*wH1b,*wH1s;
    bf *sW0b,*sW0s,*sW1b,*sW1s,*sH0b,*sH0s,*sH1b,*sH1s;
    cudaGetSymbolAddress((void**)&xe_b, g_xe_b);   cudaGetSymbolAddress((void**)&xe_s, g_xe_s);
    cudaGetSymbolAddress((void**)&xw, g_xw);
    cudaGetSymbolAddress((void**)&y0w_b, g_y0w_b); cudaGetSymbolAddress((void**)&y0w_s, g_y0w_s);
    cudaGetSymbolAddress((void**)&words_b, g_words_b); cudaGetSymbolAddress((void**)&words_s, g_words_s);
    cudaGetSymbolAddress((void**)&y0s_b, g_y0s_b); cudaGetSymbolAddress((void**)&y0s_s, g_y0s_s);
    cudaGetSymbolAddress((void**)&hwf, g_hwf);     cudaGetSymbolAddress((void**)&hsf, g_hsf);
    cudaGetSymbolAddress((void**)&hsb, g_hsb);     cudaGetSymbolAddress((void**)&hss, g_hss);
    cudaGetSymbolAddress((void**)&bar, g_bar);
    cudaGetSymbolAddress((void**)&wW0b, g_weWih0_b); cudaGetSymbolAddress((void**)&wW0s, g_weWih0_s);
    cudaGetSymbolAddress((void**)&wW1b, g_weWih1_b); cudaGetSymbolAddress((void**)&wW1s, g_weWih1_s);
    cudaGetSymbolAddress((void**)&wH0b, g_weWhh0_b); cudaGetSymbolAddress((void**)&wH0s, g_weWhh0_s);
    cudaGetSymbolAddress((void**)&wH1b, g_weWhh1_b); cudaGetSymbolAddress((void**)&wH1s, g_weWhh1_s);
    cudaGetSymbolAddress((void**)&sW0b, g_seWih0_b); cudaGetSymbolAddress((void**)&sW0s, g_seWih0_s);
    cudaGetSymbolAddress((void**)&sW1b, g_seWih1_b); cudaGetSymbolAddress((void**)&sW1s, g_seWih1_s);
    cudaGetSymbolAddress((void**)&sH0b, g_seWhh0_b); cudaGetSymbolAddress((void**)&sH0s, g_seWhh0_s);
    cudaGetSymbolAddress((void**)&sH1b, g_seWhh1_b); cudaGetSymbolAddress((void**)&sH1s, g_seWhh1_s);

    cudaFuncSetAttribute(gru_sent_persistent,
                         cudaFuncAttributeMaxDynamicSharedMemorySize, SMEM_PERS);
    cudaFuncSetAttribute(gru_word_persistent,
                         cudaFuncAttributeMaxDynamicSharedMemorySize, WORD_SMEM);
    cudaFuncSetAttribute(mma_gemm_bias,
                         cudaFuncAttributeMaxDynamicSharedMemorySize, GEMM_SMEM);

    float* hwF[2];
    float* hsF[4]; bf* hsB[4]; bf* hsS[4];
    hwF[0] = hwf; hwF[1] = hwf + (long)HWBUF_N;
    for (int i = 0; i < 4; i++) {
        hsF[i] = hsf + (long)i * HSBUF_N;
        hsB[i] = hsb + (long)i * HSBUF_N;
        hsS[i] = hss + (long)i * HSBUF_N;
    }

    /* 0. split all weights in one launch (pads zero-filled) */
    split_all<<<(unsigned)((SPLIT_TOTAL + 255) / 256), 256>>>(
        we_Wih0, wW0b, wW0s, we_Wih1, wW1b, wW1s,
        we_Whh0, wH0b, wH0s, we_Whh1, wH1b, wH1s,
        se_Wih0, sW0b, sW0s, se_Wih1, sW1b, sW1s,
        se_Whh0, sH0b, sH0s, se_Whh1, sH1b, sH1s);

    /* 1. embedding (split) */
    embed_split_k<<<(XE_N + 255) / 256, 256>>>(x, emb, xe_b, xe_s);

    /* 2. word layer0: xw precompute + register-resident recurrence */
    for (int d = 0; d < 2; d++) {
        dim3 g((3 * HW + 127) / 128, (T_LEN * NW) / 128);
        mma_gemm_bias<<<g, 256, GEMM_SMEM>>>(xe_b, xe_s,
                                  wW0b + (long)d * 3 * HW * E_DIM,
                                  wW0s + (long)d * 3 * HW * E_DIM,
                                  we_bih0 + d * 3 * HW,
                                  xw + (long)d * T_LEN * NW * 3 * HW,
                                  T_LEN * NW, 3 * HW, E_DIM);
    }
    gru_word_persistent<<<480, 128, WORD_SMEM>>>(hwF[0], xw, wH0b, wH0s,
                                                 we_bhh0, y0w_b, y0w_s);

    /* 3. word layer1: K padded to 152 */
    for (int d = 0; d < 2; d++) {
        dim3 g((3 * HW + 127) / 128, (T_LEN * NW) / 128);
        mma_gemm_bias<<<g, 256, GEMM_SMEM>>>(y0w_b, y0w_s,
                                  wW1b + (long)d * 3 * HW * HW2P,
                                  wW1s + (long)d * 3 * HW * HW2P,
                                  we_bih1 + d * 3 * HW,
                                  xw + (long)d * T_LEN * NW * 3 * HW,
                                  T_LEN * NW, 3 * HW, HW2P);
    }
    gru_word_persistent<<<480, 128, WORD_SMEM>>>(hwF[1], xw, wH1b, wH1s,
                                                 we_bhh1, (bf*)0, (bf*)0);

    /* 4. words = [hf0|hb0|hf1|hb1] split : [NW, 304-padded] */
    concat4_split<<<(NW * 4 * HW + 255) / 256, 256>>>(hwF[0], hwF[1],
                                                      words_b, words_s,
                                                      NW, HW, HWP, W4P);

    /* 5. sentence layer0: K padded to 304 + persistent recurrence */
    for (int d = 0; d < 2; d++) {
        dim3 g((3 * HS + 127) / 128, (S_LEN * B_SZ) / 128);
        mma_gemm_bias<<<g, 256, GEMM_SMEM>>>(words_b, words_s,
                                  sW0b + (long)d * 3 * HS * W4P,
                                  sW0s + (long)d * 3 * HS * W4P,
                                  se_bih0 + d * 3 * HS,
                                  xw + (long)d * S_LEN * B_SZ * 3 * HS,
                                  S_LEN * B_SZ, 3 * HS, W4P);
    }
    cudaMemsetAsync(hsF[0], 0, sizeof(float) * HSBUF_N);
    cudaMemsetAsync(hsB[0], 0, sizeof(bf) * HSBUF_N);
    cudaMemsetAsync(hsS[0], 0, sizeof(bf) * HSBUF_N);
    cudaMemsetAsync(bar, 0, 2 * sizeof(unsigned));
    gru_sent_persistent<<<NBLK_S, 256, SMEM_PERS>>>(
        sH0b, sH0s, se_bhh0, xw,
        hsF[0], hsB[0], hsS[0], hsF[1], hsB[1], hsS[1],
        y0s_b, y0s_s, bar);

    /* 6. sentence layer1: K=1400 (already aligned) */
    for (int d = 0; d < 2; d++) {
        dim3 g((3 * HS + 127) / 128, (S_LEN * B_SZ) / 128);
        mma_gemm_bias<<<g, 256, GEMM_SMEM>>>(y0s_b, y0s_s,
                                  sW1b + (long)d * 3 * HS * 2 * HS,
                                  sW1s + (long)d * 3 * HS * 2 * HS,
                                  se_bih1 + d * 3 * HS,
                                  xw + (long)d * S_LEN * B_SZ * 3 * HS,
                                  S_LEN * B_SZ, 3 * HS, 2 * HS);
    }
    cudaMemsetAsync(hsF[2], 0, sizeof(float) * HSBUF_N);
    cudaMemsetAsync(hsB[2], 0, sizeof(bf) * HSBUF_N);
    cudaMemsetAsync(hsS[2], 0, sizeof(bf) * HSBUF_N);
    cudaMemsetAsync(bar, 0, 2 * sizeof(unsigned));
    gru_sent_persistent<<<NBLK_S, 256, SMEM_PERS>>>(
        sH1b, sH1s, se_bhh1, xw,
        hsF[2], hsB[2], hsS[2], hsF[3], hsB[3], hsS[3],
        (bf*)0, (bf*)0, bar);

    /* 7. output [1, 128, 2800] = [sf0|sb0|sf1|sb1] per batch row */
    concat4_k<<<((long)B_SZ * 4 * HS + 255) / 256, 256>>>(hsF[0], hsF[2],
                                                          (float*)d_out,
                                                          B_SZ, HS, HS);
}